// round 12
// baseline (speedup 1.0000x reference)
#include <cuda_runtime.h>
#include <math.h>

#define DD 512
#define PP 36
#define PS 37                        // padded row stride: conflict-free
#define NT 512
#define EPSN 1e-12f
#define SCALE_CLS 7.0f
#define TILE_F (DD*PP)               // 18432 floats per gmem tile

// SMEM layout (floats)
#define TOFF   0                     // kept tile [512][37]
#define PAR    (DD*PS)               // stream partials [4608] (reused per phase)
#define MEANT  (PAR + TILE_F/4)      // mean of phase-1 tensor (test) [512]
#define MEANR  (MEANT + DD)          // mean of phase-2 tensor (train) [512]
#define NNO    (MEANR + DD)          // own per-position norms [40]
#define SSO    (NNO + 40)            // own selection scores [40]
#define WWO    (SSO + 40)            // own fuse weights [40]
#define REDO   (WWO + 40)            // reduction scratch [48]
#define SMEMF  (REDO + 48)
#define SMEMB  (SMEMF * 4)           // ~99.0 KB -> 2 CTAs/SM

#define MAXG 4096
__device__ float g_fuse[MAXG * 2 * DD];   // fused vectors scratch (16 MB)

__device__ __forceinline__ float warp_sum(float v) {
#pragma unroll
    for (int o = 16; o > 0; o >>= 1) v += __shfl_down_sync(0xffffffffu, v, o);
    return v;
}

__global__ __launch_bounds__(NT, 2)
void region_score_half(const float* __restrict__ ftrain,
                       const float* __restrict__ ftest,
                       const int*   __restrict__ Kp,
                       float* __restrict__ out)
{
    extern __shared__ float sm[];
    float* tile  = sm + TOFF;
    float* par   = sm + PAR;
    float* meanT = sm + MEANT;
    float* meanR = sm + MEANR;
    float* nn    = sm + NNO;
    float* ss    = sm + SSO;
    float* ww    = sm + WWO;
    float* red   = sm + REDO;

    const int g    = blockIdx.x >> 1;
    const int side = blockIdx.x & 1;    // 0: keep test, 1: keep train
    const int tid  = threadIdx.x;
    const int lane = tid & 31;
    const int wid  = tid >> 5;
    const int K    = Kp[0];

    const float* t1 = ftest  + (size_t)g * TILE_F;   // phase-1 tensor
    const float* t2 = ftrain + (size_t)g * TILE_F;   // phase-2 tensor

    // ---------------- phase 1: test tensor --------------------------------
    if (side == 0) {
        // keep: load into tile + partials
        const float4* s4 = (const float4*)t1;
#pragma unroll
        for (int k = 0; k < 9; k++) {
            int j = tid + k * NT;
            float4 a = s4[j];
            int d = j / 9;
            int p = (j - d * 9) * 4;
            int s = d * PS + p;
            tile[s] = a.x; tile[s+1] = a.y; tile[s+2] = a.z; tile[s+3] = a.w;
            par[j] = a.x + a.y + a.z + a.w;
        }
    } else {
        // stream: partials only
        const float4* s4 = (const float4*)t1;
#pragma unroll
        for (int k = 0; k < 9; k++) {
            int j = tid + k * NT;
            float4 a = s4[j];
            par[j] = a.x + a.y + a.z + a.w;
        }
    }
    __syncthreads();                    // s1: partials ready
    {
        float s = 0.f;
#pragma unroll
        for (int k = 0; k < 9; k++) s += par[9 * tid + k];
        meanT[tid] = s * (1.0f / PP);
    }
    __syncthreads();                    // s2: meanT done, par reusable

    // ---------------- phase 2: train tensor -------------------------------
    if (side == 1) {
        const float4* s4 = (const float4*)t2;
#pragma unroll
        for (int k = 0; k < 9; k++) {
            int j = tid + k * NT;
            float4 a = s4[j];
            int d = j / 9;
            int p = (j - d * 9) * 4;
            int s = d * PS + p;
            tile[s] = a.x; tile[s+1] = a.y; tile[s+2] = a.z; tile[s+3] = a.w;
            par[j] = a.x + a.y + a.z + a.w;
        }
    } else {
        const float4* s4 = (const float4*)t2;
#pragma unroll
        for (int k = 0; k < 9; k++) {
            int j = tid + k * NT;
            float4 a = s4[j];
            par[j] = a.x + a.y + a.z + a.w;
        }
    }
    __syncthreads();                    // s3: partials ready
    {
        float s = 0.f;
#pragma unroll
        for (int k = 0; k < 9; k++) s += par[9 * tid + k];
        float mr = s * (1.0f / PP);
        meanR[tid] = mr;
        // stage A partials (both sides compute; side 0 writes)
        float mt = meanT[tid];
        float a = warp_sum(mt * mr);
        float b = warp_sum(mt * mt);
        float c = warp_sum(mr * mr);
        if (lane == 0) { red[wid] = a; red[16 + wid] = b; red[32 + wid] = c; }
    }
    __syncthreads();                    // s4: means + redA ready

    if (side == 0 && wid == 0) {
        float a = (lane < 16) ? red[lane]      : 0.f;
        float b = (lane < 16) ? red[16 + lane] : 0.f;
        float c = (lane < 16) ? red[32 + lane] : 0.f;
        a = warp_sum(a); b = warp_sum(b); c = warp_sum(c);
        if (lane == 0) {
            float den = fmaxf(sqrtf(b), EPSN) * fmaxf(sqrtf(c), EPSN);
            out[g] = SCALE_CLS * a / den;
        }
    }

    // ---------------- stage B (own side): norms + selection scores ---------
    {
        const float* M = side ? meanT : meanR;   // other tensor's mean
        float mc[16];
#pragma unroll
        for (int i = 0; i < 16; i++) mc[i] = M[lane + 32 * i];
#pragma unroll
        for (int rr = 0; rr < 3; rr++) {
            if (rr == 2 && wid >= 4) break;
            const int p = wid + 16 * rr;         // 0..35
            float a2 = 0.f, ta = 0.f;
#pragma unroll
            for (int i = 0; i < 16; i++) {
                float x = tile[(lane + 32 * i) * PS + p];
                a2 += x * x;
                ta += x * mc[i];
            }
            a2 = warp_sum(a2);
            ta = warp_sum(ta);
            if (lane == 0) {
                float n = fmaxf(sqrtf(a2), EPSN);
                nn[p] = n;
                ss[p] = ta / n;   // positive constant factors cancel in ranking
            }
        }
    }
    __syncthreads();                    // s5: scores/norms ready

    // ---------------- stage C: top-K via rank counting ---------------------
    if (tid < PP) {
        const float sv = ss[tid];
        int rank = 0;
#pragma unroll
        for (int q = 0; q < PP; q++) {
            float o = ss[q];
            rank += (o > sv) || (o == sv && q < tid);   // lower index wins ties
        }
        ww[tid] = (rank < K) ? (1.0f / nn[tid]) : 0.0f;
    }
    __syncthreads();                    // s6: weights ready

    // ---------------- stage D: fused vector -> global scratch --------------
    {
        const float* row = tile + tid * PS;
        float u = 0.f;
#pragma unroll
        for (int p = 0; p < PP; p++) u += row[p] * ww[p];   // ww reads broadcast
        g_fuse[((size_t)g * 2 + side) * DD + tid] = u;
    }
}

__global__ __launch_bounds__(NT, 2)
void region_score_final(float* __restrict__ out, int halfOut)
{
    __shared__ float red[48];
    const int g    = blockIdx.x;
    const int tid  = threadIdx.x;
    const int lane = tid & 31;
    const int wid  = tid >> 5;

    float u = g_fuse[((size_t)g * 2 + 0) * DD + tid];
    float v = g_fuse[((size_t)g * 2 + 1) * DD + tid];
    float a = warp_sum(u * v);
    float b = warp_sum(u * u);
    float c = warp_sum(v * v);
    if (lane == 0) { red[wid] = a; red[16 + wid] = b; red[32 + wid] = c; }
    __syncthreads();
    if (wid == 0) {
        float x = (lane < 16) ? red[lane]      : 0.f;
        float y = (lane < 16) ? red[16 + lane] : 0.f;
        float z = (lane < 16) ? red[32 + lane] : 0.f;
        x = warp_sum(x); y = warp_sum(y); z = warp_sum(z);
        if (lane == 0) {
            float den = fmaxf(sqrtf(y), EPSN) * fmaxf(sqrtf(z), EPSN);
            out[halfOut + g] = SCALE_CLS * x / den;
        }
    }
}

extern "C" void kernel_launch(void* const* d_in, const int* in_sizes, int n_in,
                              void* d_out, int out_size)
{
    const float* ftrain = (const float*)d_in[0];
    const float* ftest  = (const float*)d_in[1];
    const int*   Kp     = (const int*)d_in[2];
    float* out = (float*)d_out;

    const int groups  = in_sizes[0] / (DD * PP);   // 1500
    const int halfOut = out_size / 2;              // 1500

    cudaFuncSetAttribute(region_score_half,
                         cudaFuncAttributeMaxDynamicSharedMemorySize, SMEMB);
    region_score_half<<<groups * 2, NT, SMEMB>>>(ftrain, ftest, Kp, out);
    region_score_final<<<groups, NT>>>(out, halfOut);
}